// round 1
// baseline (speedup 1.0000x reference)
#include <cuda_runtime.h>

#define TPB 256

struct CamParams {
    float c2w[9];
    float t[3];
    float Kinv[9];
    float mult;
};

__global__ void __launch_bounds__(TPB)
mono_gaussian_adapter_kernel(
    const float* __restrict__ ext,        // (B,1,4,4)
    const float* __restrict__ intr,       // (B,1,3,3)
    const float* __restrict__ coords,     // (B,N,2)
    const float* __restrict__ depths,     // (B,N)
    const float* __restrict__ opac,       // (B,N)
    const float* __restrict__ rg,         // (B,N,19)
    const unsigned int* __restrict__ hptr,
    const unsigned int* __restrict__ wptr,
    float* __restrict__ out,
    int N)
{
    __shared__ CamParams cam;
    const int b = blockIdx.y;

    if (threadIdx.x == 0) {
        const float* E = ext + b * 16;
        const float* K = intr + b * 9;
#pragma unroll
        for (int i = 0; i < 3; i++) {
            cam.c2w[i * 3 + 0] = E[i * 4 + 0];
            cam.c2w[i * 3 + 1] = E[i * 4 + 1];
            cam.c2w[i * 3 + 2] = E[i * 4 + 2];
            cam.t[i]           = E[i * 4 + 3];
        }
        float k00 = K[0], k01 = K[1], k02 = K[2];
        float k10 = K[3], k11 = K[4], k12 = K[5];
        float k20 = K[6], k21 = K[7], k22 = K[8];
        float det = k00 * (k11 * k22 - k12 * k21)
                  - k01 * (k10 * k22 - k12 * k20)
                  + k02 * (k10 * k21 - k11 * k20);
        float id = 1.0f / det;
        cam.Kinv[0] = (k11 * k22 - k12 * k21) * id;
        cam.Kinv[1] = (k02 * k21 - k01 * k22) * id;
        cam.Kinv[2] = (k01 * k12 - k02 * k11) * id;
        cam.Kinv[3] = (k12 * k20 - k10 * k22) * id;
        cam.Kinv[4] = (k00 * k22 - k02 * k20) * id;
        cam.Kinv[5] = (k02 * k10 - k00 * k12) * id;
        cam.Kinv[6] = (k10 * k21 - k11 * k20) * id;
        cam.Kinv[7] = (k01 * k20 - k00 * k21) * id;
        cam.Kinv[8] = (k00 * k11 - k01 * k10) * id;

        // h/w scalars: decode defensively (int32 vs float32 bit pattern)
        unsigned hv = hptr[0], wv = wptr[0];
        float hf = (hv < 100000u) ? (float)hv : __uint_as_float(hv);
        float wf = (wv < 100000u) ? (float)wv : __uint_as_float(wv);
        float px = 1.0f / wf, py = 1.0f / hf;
        float det2 = k00 * k11 - k01 * k10;
        // sum over i of (0.1 * inv2 @ [px,py]) = 0.1*((d*px - b*py) + (-c*px + a*py))/det2
        cam.mult = 0.1f * ((k11 * px - k01 * py) + (-k10 * px + k00 * py)) / det2;
    }
    __syncthreads();

    const int n = blockIdx.x * TPB + threadIdx.x;
    if (n >= N) return;
    const long long idx = (long long)b * N + n;
    const long long BN  = (long long)gridDim.y * N;

    // ---- loads ----
    const float2 uv   = ((const float2*)coords)[idx];
    const float  depth = depths[idx];
    const float  op    = opac[idx];
    float g[19];
    const float* grow = rg + idx * 19;
#pragma unroll
    for (int i = 0; i < 19; i++) g[i] = grow[i];

    // ---- scales: 0.5 + 14.5*sigmoid, then * depth * multiplier ----
    float sc[3];
#pragma unroll
    for (int i = 0; i < 3; i++) {
        float s = 1.0f / (1.0f + __expf(-g[i]));
        sc[i] = (0.5f + 14.5f * s) * depth * cam.mult;
    }

    // ---- quaternion normalize (norm + eps, matching ref) ----
    float qw = g[3], qx = g[4], qy = g[5], qz = g[6];
    float qn = sqrtf(qw * qw + qx * qx + qy * qy + qz * qz) + 1e-8f;
    float qinv = 1.0f / qn;
    qw *= qinv; qx *= qinv; qy *= qinv; qz *= qinv;

    // ---- rotation matrix ----
    float R[9];
    R[0] = 1.f - 2.f * (qy * qy + qz * qz);
    R[1] = 2.f * (qx * qy - qw * qz);
    R[2] = 2.f * (qx * qz + qw * qy);
    R[3] = 2.f * (qx * qy + qw * qz);
    R[4] = 1.f - 2.f * (qx * qx + qz * qz);
    R[5] = 2.f * (qy * qz - qw * qx);
    R[6] = 2.f * (qx * qz - qw * qy);
    R[7] = 2.f * (qy * qz + qw * qx);
    R[8] = 1.f - 2.f * (qx * qx + qy * qy);

    // ---- cov = (W R diag(s)) (W R diag(s))^T ----
    float T[9];
#pragma unroll
    for (int i = 0; i < 3; i++)
#pragma unroll
        for (int j = 0; j < 3; j++)
            T[i * 3 + j] = (cam.c2w[i * 3 + 0] * R[0 * 3 + j]
                          + cam.c2w[i * 3 + 1] * R[1 * 3 + j]
                          + cam.c2w[i * 3 + 2] * R[2 * 3 + j]) * sc[j];
    float cov[9];
#pragma unroll
    for (int i = 0; i < 3; i++)
#pragma unroll
        for (int j = 0; j <= i; j++) {
            float v = T[i * 3 + 0] * T[j * 3 + 0]
                    + T[i * 3 + 1] * T[j * 3 + 1]
                    + T[i * 3 + 2] * T[j * 3 + 2];
            cov[i * 3 + j] = v;
            cov[j * 3 + i] = v;
        }

    // ---- means: t + c2w @ normalize(Kinv @ [u,v,1]) * depth ----
    float d0 = cam.Kinv[0] * uv.x + cam.Kinv[1] * uv.y + cam.Kinv[2];
    float d1 = cam.Kinv[3] * uv.x + cam.Kinv[4] * uv.y + cam.Kinv[5];
    float d2 = cam.Kinv[6] * uv.x + cam.Kinv[7] * uv.y + cam.Kinv[8];
    float rn = rsqrtf(d0 * d0 + d1 * d1 + d2 * d2);
    d0 *= rn; d1 *= rn; d2 *= rn;
    float m[3];
#pragma unroll
    for (int i = 0; i < 3; i++)
        m[i] = cam.t[i] + (cam.c2w[i * 3 + 0] * d0
                         + cam.c2w[i * 3 + 1] * d1
                         + cam.c2w[i * 3 + 2] * d2) * depth;

    // ---- harmonics: sh0 | D1 @ (0.025 * sh1..3)  (D1 = c2w[p,:][:,p], p=(1,2,0)) ----
    float har[12];
    const int p0 = 1, p1 = 2, p2 = 0;
    const int pr[3] = {p0, p1, p2};
#pragma unroll
    for (int c = 0; c < 3; c++) {
        har[c * 4 + 0] = g[7 + c * 4 + 0];
        float s1 = g[7 + c * 4 + 1] * 0.025f;
        float s2 = g[7 + c * 4 + 2] * 0.025f;
        float s3 = g[7 + c * 4 + 3] * 0.025f;
#pragma unroll
        for (int i = 0; i < 3; i++) {
            int ri = pr[i];
            har[c * 4 + 1 + i] = cam.c2w[ri * 3 + p0] * s1
                               + cam.c2w[ri * 3 + p1] * s2
                               + cam.c2w[ri * 3 + p2] * s3;
        }
    }

    // ---- stores (tuple outputs concatenated flat) ----
    float* means_o = out;                 // BN*3
    float* cov_o   = out + BN * 3;        // BN*9
    float* har_o   = out + BN * 12;       // BN*12
    float* op_o    = out + BN * 24;       // BN*1
    float* sc_o    = out + BN * 25;       // BN*3
    float* rot_o   = out + BN * 28;       // BN*4

#pragma unroll
    for (int i = 0; i < 3; i++) means_o[idx * 3 + i] = m[i];
#pragma unroll
    for (int i = 0; i < 9; i++) cov_o[idx * 9 + i] = cov[i];
#pragma unroll
    for (int i = 0; i < 12; i++) har_o[idx * 12 + i] = har[i];
    op_o[idx] = op;
#pragma unroll
    for (int i = 0; i < 3; i++) sc_o[idx * 3 + i] = sc[i];
    ((float4*)rot_o)[idx] = make_float4(qw, qx, qy, qz);
}

extern "C" void kernel_launch(void* const* d_in, const int* in_sizes, int n_in,
                              void* d_out, int out_size)
{
    const float* ext    = (const float*)d_in[0];
    const float* intr   = (const float*)d_in[1];
    const float* coords = (const float*)d_in[2];
    const float* depths = (const float*)d_in[3];
    const float* opac   = (const float*)d_in[4];
    const float* rg     = (const float*)d_in[5];
    const unsigned int* hptr = (const unsigned int*)d_in[6];
    const unsigned int* wptr = (const unsigned int*)d_in[7];
    float* out = (float*)d_out;

    const int B = in_sizes[0] / 16;            // extrinsics: B*1*4*4
    const int N = in_sizes[3] / B;             // depths: B*N

    dim3 grid((N + TPB - 1) / TPB, B);
    mono_gaussian_adapter_kernel<<<grid, TPB>>>(
        ext, intr, coords, depths, opac, rg, hptr, wptr, out, N);
}

// round 4
// speedup vs baseline: 1.4658x; 1.4658x over previous
#include <cuda_runtime.h>

#define TPB 128

struct CamParams {
    float c2w[9];
    float t[3];
    float Kinv[9];
    float mult;
};

__global__ void __launch_bounds__(TPB)
mono_gaussian_adapter_kernel(
    const float* __restrict__ ext,        // (B,1,4,4)
    const float* __restrict__ intr,       // (B,1,3,3)
    const float* __restrict__ coords,     // (B,N,2)
    const float* __restrict__ depths,     // (B,N)
    const float* __restrict__ opac,       // (B,N)
    const float* __restrict__ rg,         // (B,N,19)
    const unsigned int* __restrict__ hptr,
    const unsigned int* __restrict__ wptr,
    float* __restrict__ out,
    int N)
{
    // 16B alignment is required: buf is accessed through a float4* view (LDS.128/STS.128).
    __shared__ __align__(16) float buf[TPB * 19];
    __shared__ CamParams cam;
    const int b   = blockIdx.y;
    const int tid = threadIdx.x;

    if (tid == 0) {
        const float* E = ext + b * 16;
        const float* K = intr + b * 9;
#pragma unroll
        for (int i = 0; i < 3; i++) {
            cam.c2w[i * 3 + 0] = E[i * 4 + 0];
            cam.c2w[i * 3 + 1] = E[i * 4 + 1];
            cam.c2w[i * 3 + 2] = E[i * 4 + 2];
            cam.t[i]           = E[i * 4 + 3];
        }
        float k00 = K[0], k01 = K[1], k02 = K[2];
        float k10 = K[3], k11 = K[4], k12 = K[5];
        float k20 = K[6], k21 = K[7], k22 = K[8];
        float det = k00 * (k11 * k22 - k12 * k21)
                  - k01 * (k10 * k22 - k12 * k20)
                  + k02 * (k10 * k21 - k11 * k20);
        float id = 1.0f / det;
        cam.Kinv[0] = (k11 * k22 - k12 * k21) * id;
        cam.Kinv[1] = (k02 * k21 - k01 * k22) * id;
        cam.Kinv[2] = (k01 * k12 - k02 * k11) * id;
        cam.Kinv[3] = (k12 * k20 - k10 * k22) * id;
        cam.Kinv[4] = (k00 * k22 - k02 * k20) * id;
        cam.Kinv[5] = (k02 * k10 - k00 * k12) * id;
        cam.Kinv[6] = (k10 * k21 - k11 * k20) * id;
        cam.Kinv[7] = (k01 * k20 - k00 * k21) * id;
        cam.Kinv[8] = (k00 * k11 - k01 * k10) * id;

        unsigned hv = hptr[0], wv = wptr[0];
        float hf = (hv < 100000u) ? (float)hv : __uint_as_float(hv);
        float wf = (wv < 100000u) ? (float)wv : __uint_as_float(wv);
        float px = 1.0f / wf, py = 1.0f / hf;
        float det2 = k00 * k11 - k01 * k10;
        cam.mult = 0.1f * ((k11 * px - k01 * py) + (-k10 * px + k00 * py)) / det2;
    }
    __syncthreads();

    const int n = blockIdx.x * TPB + tid;
    const long long idx0 = (long long)b * N + (long long)blockIdx.x * TPB;
    const long long idx  = idx0 + tid;
    const long long BN   = (long long)gridDim.y * N;
    const bool full = ((long long)blockIdx.x * TPB + TPB) <= N;
    const bool live = n < N;

    float4* buf4 = (float4*)buf;

    // ---- input: raw_gaussians staged coalesced ----
    float g[19];
    if (full) {
        const float4* src4 = (const float4*)(rg + idx0 * 19);
        for (int j = tid; j < TPB * 19 / 4; j += TPB) buf4[j] = src4[j];
        __syncthreads();
#pragma unroll
        for (int i = 0; i < 19; i++) g[i] = buf[tid * 19 + i];
    } else if (live) {
        const float* grow = rg + idx * 19;
#pragma unroll
        for (int i = 0; i < 19; i++) g[i] = grow[i];
    }

    float2 uv = make_float2(0.f, 0.f);
    float depth = 0.f, op = 0.f;
    if (live) {
        uv    = ((const float2*)coords)[idx];
        depth = depths[idx];
        op    = opac[idx];
    }

    // ---- compute ----
    float sc[3];
#pragma unroll
    for (int i = 0; i < 3; i++) {
        float s = 1.0f / (1.0f + __expf(-g[i]));
        sc[i] = (0.5f + 14.5f * s) * depth * cam.mult;
    }

    float qw = g[3], qx = g[4], qy = g[5], qz = g[6];
    float qn = sqrtf(qw * qw + qx * qx + qy * qy + qz * qz) + 1e-8f;
    float qinv = 1.0f / qn;
    qw *= qinv; qx *= qinv; qy *= qinv; qz *= qinv;

    float R[9];
    R[0] = 1.f - 2.f * (qy * qy + qz * qz);
    R[1] = 2.f * (qx * qy - qw * qz);
    R[2] = 2.f * (qx * qz + qw * qy);
    R[3] = 2.f * (qx * qy + qw * qz);
    R[4] = 1.f - 2.f * (qx * qx + qz * qz);
    R[5] = 2.f * (qy * qz - qw * qx);
    R[6] = 2.f * (qx * qz - qw * qy);
    R[7] = 2.f * (qy * qz + qw * qx);
    R[8] = 1.f - 2.f * (qx * qx + qy * qy);

    float T[9];
#pragma unroll
    for (int i = 0; i < 3; i++)
#pragma unroll
        for (int j = 0; j < 3; j++)
            T[i * 3 + j] = (cam.c2w[i * 3 + 0] * R[0 * 3 + j]
                          + cam.c2w[i * 3 + 1] * R[1 * 3 + j]
                          + cam.c2w[i * 3 + 2] * R[2 * 3 + j]) * sc[j];
    float cov[9];
#pragma unroll
    for (int i = 0; i < 3; i++)
#pragma unroll
        for (int j = 0; j <= i; j++) {
            float v = T[i * 3 + 0] * T[j * 3 + 0]
                    + T[i * 3 + 1] * T[j * 3 + 1]
                    + T[i * 3 + 2] * T[j * 3 + 2];
            cov[i * 3 + j] = v;
            cov[j * 3 + i] = v;
        }

    float d0 = cam.Kinv[0] * uv.x + cam.Kinv[1] * uv.y + cam.Kinv[2];
    float d1 = cam.Kinv[3] * uv.x + cam.Kinv[4] * uv.y + cam.Kinv[5];
    float d2 = cam.Kinv[6] * uv.x + cam.Kinv[7] * uv.y + cam.Kinv[8];
    float rn = rsqrtf(d0 * d0 + d1 * d1 + d2 * d2);
    d0 *= rn; d1 *= rn; d2 *= rn;
    float m[3];
#pragma unroll
    for (int i = 0; i < 3; i++)
        m[i] = cam.t[i] + (cam.c2w[i * 3 + 0] * d0
                         + cam.c2w[i * 3 + 1] * d1
                         + cam.c2w[i * 3 + 2] * d2) * depth;

    float har[12];
    const int pr[3] = {1, 2, 0};
#pragma unroll
    for (int c = 0; c < 3; c++) {
        har[c * 4 + 0] = g[7 + c * 4 + 0];
        float s1 = g[7 + c * 4 + 1] * 0.025f;
        float s2 = g[7 + c * 4 + 2] * 0.025f;
        float s3 = g[7 + c * 4 + 3] * 0.025f;
#pragma unroll
        for (int i = 0; i < 3; i++) {
            int ri = pr[i];
            har[c * 4 + 1 + i] = cam.c2w[ri * 3 + 1] * s1
                               + cam.c2w[ri * 3 + 2] * s2
                               + cam.c2w[ri * 3 + 0] * s3;
        }
    }

    // ---- output section pointers ----
    float* means_o = out;                 // BN*3
    float* cov_o   = out + BN * 3;        // BN*9
    float* har_o   = out + BN * 12;       // BN*12
    float* op_o    = out + BN * 24;       // BN*1
    float* sc_o    = out + BN * 25;       // BN*3
    float* rot_o   = out + BN * 28;       // BN*4

    // direct stores (already coalesced): opacity (stride 1), rotations (float4/lane)
    if (live) {
        op_o[idx] = op;
        ((float4*)rot_o)[idx] = make_float4(qw, qx, qy, qz);
    }

    if (full) {
        // ---- staged coalesced stores ----
        __syncthreads();  // everyone done reading g from buf
        // cov (stride 9)
#pragma unroll
        for (int i = 0; i < 9; i++) buf[tid * 9 + i] = cov[i];
        __syncthreads();
        {
            float4* dst4 = (float4*)(cov_o + idx0 * 9);
            for (int j = tid; j < TPB * 9 / 4; j += TPB) dst4[j] = buf4[j];
        }
        __syncthreads();
        // harmonics (stride 12)
#pragma unroll
        for (int i = 0; i < 12; i++) buf[tid * 12 + i] = har[i];
        __syncthreads();
        {
            float4* dst4 = (float4*)(har_o + idx0 * 12);
            for (int j = tid; j < TPB * 12 / 4; j += TPB) dst4[j] = buf4[j];
        }
        __syncthreads();
        // means (stride 3) and scales (stride 3) packed side by side
#pragma unroll
        for (int i = 0; i < 3; i++) {
            buf[tid * 3 + i]           = m[i];
            buf[TPB * 3 + tid * 3 + i] = sc[i];
        }
        __syncthreads();
        {
            float4* dstm = (float4*)(means_o + idx0 * 3);
            float4* dsts = (float4*)(sc_o    + idx0 * 3);
            for (int j = tid; j < TPB * 3 / 4; j += TPB) {
                dstm[j] = buf4[j];
                dsts[j] = buf4[TPB * 3 / 4 + j];
            }
        }
    } else if (live) {
#pragma unroll
        for (int i = 0; i < 3; i++) means_o[idx * 3 + i] = m[i];
#pragma unroll
        for (int i = 0; i < 9; i++) cov_o[idx * 9 + i] = cov[i];
#pragma unroll
        for (int i = 0; i < 12; i++) har_o[idx * 12 + i] = har[i];
#pragma unroll
        for (int i = 0; i < 3; i++) sc_o[idx * 3 + i] = sc[i];
    }
}

extern "C" void kernel_launch(void* const* d_in, const int* in_sizes, int n_in,
                              void* d_out, int out_size)
{
    const float* ext    = (const float*)d_in[0];
    const float* intr   = (const float*)d_in[1];
    const float* coords = (const float*)d_in[2];
    const float* depths = (const float*)d_in[3];
    const float* opac   = (const float*)d_in[4];
    const float* rg     = (const float*)d_in[5];
    const unsigned int* hptr = (const unsigned int*)d_in[6];
    const unsigned int* wptr = (const unsigned int*)d_in[7];
    float* out = (float*)d_out;

    const int B = in_sizes[0] / 16;            // extrinsics: B*1*4*4
    const int N = in_sizes[3] / B;             // depths: B*N

    dim3 grid((N + TPB - 1) / TPB, B);
    mono_gaussian_adapter_kernel<<<grid, TPB>>>(
        ext, intr, coords, depths, opac, rg, hptr, wptr, out, N);
}

// round 5
// speedup vs baseline: 1.8011x; 1.2287x over previous
#include <cuda_runtime.h>

#define TPB 128

struct CamParams {
    float c2w[9];
    float t[3];
    float Kinv[9];
    float mult;
};

__global__ void __launch_bounds__(TPB)
mono_gaussian_adapter_kernel(
    const float* __restrict__ ext,        // (B,1,4,4)
    const float* __restrict__ intr,       // (B,1,3,3)
    const float* __restrict__ coords,     // (B,N,2)
    const float* __restrict__ depths,     // (B,N)
    const float* __restrict__ opac,       // (B,N)
    const float* __restrict__ rg,         // (B,N,19)
    const unsigned int* __restrict__ hptr,
    const unsigned int* __restrict__ wptr,
    float* __restrict__ out,
    int N)
{
    // 16B alignment: both buffers are viewed as float4*.
    __shared__ __align__(16) float ibuf[TPB * 19];   // input staging
    __shared__ __align__(16) float obuf[TPB * 27];   // cov[0,9T) har[9T,21T) means[21T,24T) sc[24T,27T)
    __shared__ CamParams cam;
    const int b   = blockIdx.y;
    const int tid = threadIdx.x;

    if (tid == 0) {
        const float* E = ext + b * 16;
        const float* K = intr + b * 9;
#pragma unroll
        for (int i = 0; i < 3; i++) {
            cam.c2w[i * 3 + 0] = E[i * 4 + 0];
            cam.c2w[i * 3 + 1] = E[i * 4 + 1];
            cam.c2w[i * 3 + 2] = E[i * 4 + 2];
            cam.t[i]           = E[i * 4 + 3];
        }
        float k00 = K[0], k01 = K[1], k02 = K[2];
        float k10 = K[3], k11 = K[4], k12 = K[5];
        float k20 = K[6], k21 = K[7], k22 = K[8];
        float det = k00 * (k11 * k22 - k12 * k21)
                  - k01 * (k10 * k22 - k12 * k20)
                  + k02 * (k10 * k21 - k11 * k20);
        float id = 1.0f / det;
        cam.Kinv[0] = (k11 * k22 - k12 * k21) * id;
        cam.Kinv[1] = (k02 * k21 - k01 * k22) * id;
        cam.Kinv[2] = (k01 * k12 - k02 * k11) * id;
        cam.Kinv[3] = (k12 * k20 - k10 * k22) * id;
        cam.Kinv[4] = (k00 * k22 - k02 * k20) * id;
        cam.Kinv[5] = (k02 * k10 - k00 * k12) * id;
        cam.Kinv[6] = (k10 * k21 - k11 * k20) * id;
        cam.Kinv[7] = (k01 * k20 - k00 * k21) * id;
        cam.Kinv[8] = (k00 * k11 - k01 * k10) * id;

        unsigned hv = hptr[0], wv = wptr[0];
        float hf = (hv < 100000u) ? (float)hv : __uint_as_float(hv);
        float wf = (wv < 100000u) ? (float)wv : __uint_as_float(wv);
        float px = 1.0f / wf, py = 1.0f / hf;
        float det2 = k00 * k11 - k01 * k10;
        cam.mult = 0.1f * ((k11 * px - k01 * py) + (-k10 * px + k00 * py)) / det2;
    }
    __syncthreads();

    // All indices fit in 32 bits: total out floats = B*N*32 = 33.5M < 2^31.
    const int n    = blockIdx.x * TPB + tid;
    const int idx0 = b * N + blockIdx.x * TPB;
    const int idx  = idx0 + tid;
    const int BN   = (int)gridDim.y * N;
    const bool full = (blockIdx.x * TPB + TPB) <= N;
    const bool live = n < N;

    float4* ibuf4 = (float4*)ibuf;

    // ---- input: raw_gaussians staged coalesced ----
    float g[19];
    if (full) {
        const float4* src4 = (const float4*)(rg + (size_t)idx0 * 19);
        for (int j = tid; j < TPB * 19 / 4; j += TPB) ibuf4[j] = src4[j];
        __syncthreads();
#pragma unroll
        for (int i = 0; i < 19; i++) g[i] = ibuf[tid * 19 + i];   // stride 19 (odd): conflict-free
    } else if (live) {
        const float* grow = rg + (size_t)idx * 19;
#pragma unroll
        for (int i = 0; i < 19; i++) g[i] = grow[i];
    }

    float2 uv = make_float2(0.f, 0.f);
    float depth = 0.f, op = 0.f;
    if (live) {
        uv    = ((const float2*)coords)[idx];
        depth = depths[idx];
        op    = opac[idx];
    }

    // ---- compute ----
    float sc[3];
#pragma unroll
    for (int i = 0; i < 3; i++) {
        float s = 1.0f / (1.0f + __expf(-g[i]));
        sc[i] = (0.5f + 14.5f * s) * depth * cam.mult;
    }

    float qw = g[3], qx = g[4], qy = g[5], qz = g[6];
    float qn = sqrtf(qw * qw + qx * qx + qy * qy + qz * qz) + 1e-8f;
    float qinv = 1.0f / qn;
    qw *= qinv; qx *= qinv; qy *= qinv; qz *= qinv;

    float R[9];
    R[0] = 1.f - 2.f * (qy * qy + qz * qz);
    R[1] = 2.f * (qx * qy - qw * qz);
    R[2] = 2.f * (qx * qz + qw * qy);
    R[3] = 2.f * (qx * qy + qw * qz);
    R[4] = 1.f - 2.f * (qx * qx + qz * qz);
    R[5] = 2.f * (qy * qz - qw * qx);
    R[6] = 2.f * (qx * qz - qw * qy);
    R[7] = 2.f * (qy * qz + qw * qx);
    R[8] = 1.f - 2.f * (qx * qx + qy * qy);

    float T[9];
#pragma unroll
    for (int i = 0; i < 3; i++)
#pragma unroll
        for (int j = 0; j < 3; j++)
            T[i * 3 + j] = (cam.c2w[i * 3 + 0] * R[0 * 3 + j]
                          + cam.c2w[i * 3 + 1] * R[1 * 3 + j]
                          + cam.c2w[i * 3 + 2] * R[2 * 3 + j]) * sc[j];
    float cov[9];
#pragma unroll
    for (int i = 0; i < 3; i++)
#pragma unroll
        for (int j = 0; j <= i; j++) {
            float v = T[i * 3 + 0] * T[j * 3 + 0]
                    + T[i * 3 + 1] * T[j * 3 + 1]
                    + T[i * 3 + 2] * T[j * 3 + 2];
            cov[i * 3 + j] = v;
            cov[j * 3 + i] = v;
        }

    float d0 = cam.Kinv[0] * uv.x + cam.Kinv[1] * uv.y + cam.Kinv[2];
    float d1 = cam.Kinv[3] * uv.x + cam.Kinv[4] * uv.y + cam.Kinv[5];
    float d2 = cam.Kinv[6] * uv.x + cam.Kinv[7] * uv.y + cam.Kinv[8];
    float rn = rsqrtf(d0 * d0 + d1 * d1 + d2 * d2);
    d0 *= rn; d1 *= rn; d2 *= rn;
    float m[3];
#pragma unroll
    for (int i = 0; i < 3; i++)
        m[i] = cam.t[i] + (cam.c2w[i * 3 + 0] * d0
                         + cam.c2w[i * 3 + 1] * d1
                         + cam.c2w[i * 3 + 2] * d2) * depth;

    float har[12];
    const int pr[3] = {1, 2, 0};
#pragma unroll
    for (int c = 0; c < 3; c++) {
        har[c * 4 + 0] = g[7 + c * 4 + 0];
        float s1 = g[7 + c * 4 + 1] * 0.025f;
        float s2 = g[7 + c * 4 + 2] * 0.025f;
        float s3 = g[7 + c * 4 + 3] * 0.025f;
#pragma unroll
        for (int i = 0; i < 3; i++) {
            int ri = pr[i];
            har[c * 4 + 1 + i] = cam.c2w[ri * 3 + 1] * s1
                               + cam.c2w[ri * 3 + 2] * s2
                               + cam.c2w[ri * 3 + 0] * s3;
        }
    }

    // ---- output section pointers ----
    float* means_o = out;                 // BN*3
    float* cov_o   = out + BN * 3;        // BN*9
    float* har_o   = out + BN * 12;       // BN*12
    float* op_o    = out + BN * 24;       // BN*1
    float* sc_o    = out + BN * 25;       // BN*3
    float* rot_o   = out + BN * 28;       // BN*4

    // direct stores (already coalesced): opacity (stride 1), rotations (float4/lane)
    if (live) {
        op_o[idx] = op;
        ((float4*)rot_o)[idx] = make_float4(qw, qx, qy, qz);
    }

    if (full) {
        // ---- stage all outputs (no sync needed: obuf disjoint from ibuf) ----
        // cov: scalar, stride 9 (odd) -> conflict-free
#pragma unroll
        for (int i = 0; i < 9; i++) obuf[tid * 9 + i] = cov[i];
        // har: vector STS.128, float4-stride 3 -> conflict-free (12t mod 32 distinct per phase)
        {
            float4* h4 = (float4*)(obuf + 9 * TPB);
#pragma unroll
            for (int c = 0; c < 3; c++)
                h4[tid * 3 + c] = make_float4(har[c * 4 + 0], har[c * 4 + 1],
                                              har[c * 4 + 2], har[c * 4 + 3]);
        }
        // means & scales: scalar, stride 3 (odd) -> conflict-free
#pragma unroll
        for (int i = 0; i < 3; i++) {
            obuf[21 * TPB + tid * 3 + i] = m[i];
            obuf[24 * TPB + tid * 3 + i] = sc[i];
        }
        __syncthreads();

        // ---- single combined coalesced flush ----
        const float4* s4 = (const float4*)obuf;
        float4* dc = (float4*)(cov_o   + (size_t)idx0 * 9);
        for (int j = tid; j < TPB * 9 / 4; j += TPB)  dc[j] = s4[j];
        float4* dh = (float4*)(har_o   + (size_t)idx0 * 12);
        for (int j = tid; j < TPB * 12 / 4; j += TPB) dh[j] = s4[TPB * 9 / 4 + j];
        float4* dm = (float4*)(means_o + (size_t)idx0 * 3);
        if (tid < TPB * 3 / 4) dm[tid] = s4[TPB * 21 / 4 + tid];
        float4* ds = (float4*)(sc_o    + (size_t)idx0 * 3);
        if (tid < TPB * 3 / 4) ds[tid] = s4[TPB * 24 / 4 + tid];
    } else if (live) {
#pragma unroll
        for (int i = 0; i < 3; i++) means_o[(size_t)idx * 3 + i] = m[i];
#pragma unroll
        for (int i = 0; i < 9; i++) cov_o[(size_t)idx * 9 + i] = cov[i];
#pragma unroll
        for (int i = 0; i < 12; i++) har_o[(size_t)idx * 12 + i] = har[i];
#pragma unroll
        for (int i = 0; i < 3; i++) sc_o[(size_t)idx * 3 + i] = sc[i];
    }
}

extern "C" void kernel_launch(void* const* d_in, const int* in_sizes, int n_in,
                              void* d_out, int out_size)
{
    const float* ext    = (const float*)d_in[0];
    const float* intr   = (const float*)d_in[1];
    const float* coords = (const float*)d_in[2];
    const float* depths = (const float*)d_in[3];
    const float* opac   = (const float*)d_in[4];
    const float* rg     = (const float*)d_in[5];
    const unsigned int* hptr = (const unsigned int*)d_in[6];
    const unsigned int* wptr = (const unsigned int*)d_in[7];
    float* out = (float*)d_out;

    const int B = in_sizes[0] / 16;            // extrinsics: B*1*4*4
    const int N = in_sizes[3] / B;             // depths: B*N

    dim3 grid((N + TPB - 1) / TPB, B);
    mono_gaussian_adapter_kernel<<<grid, TPB>>>(
        ext, intr, coords, depths, opac, rg, hptr, wptr, out, N);
}

// round 6
// speedup vs baseline: 1.9497x; 1.0825x over previous
#include <cuda_runtime.h>

#define TPB 128

struct CamParams {
    float c2w[9];
    float t[3];
    float Kinv[9];
    float mult;
};

__global__ void __launch_bounds__(TPB, 12)
mono_gaussian_adapter_kernel(
    const float* __restrict__ ext,        // (B,1,4,4)
    const float* __restrict__ intr,       // (B,1,3,3)
    const float* __restrict__ coords,     // (B,N,2)
    const float* __restrict__ depths,     // (B,N)
    const float* __restrict__ opac,       // (B,N)
    const float* __restrict__ rg,         // (B,N,19)
    const unsigned int* __restrict__ hptr,
    const unsigned int* __restrict__ wptr,
    float* __restrict__ out,
    int N)
{
    // Single staging buffer, reused: input rg (19T floats) then outputs (27T floats).
    // 16B alignment required for the float4* views.
    __shared__ __align__(16) float buf[TPB * 27];
    __shared__ CamParams cam;
    const int b   = blockIdx.y;
    const int tid = threadIdx.x;

    // All indices fit in 32 bits: total out floats = B*N*32 = 33.5M < 2^31.
    const int n    = blockIdx.x * TPB + tid;
    const int idx0 = b * N + blockIdx.x * TPB;
    const int idx  = idx0 + tid;
    const int BN   = (int)gridDim.y * N;
    const bool full = (blockIdx.x * TPB + TPB) <= N;
    const bool live = n < N;

    float4* buf4 = (float4*)buf;

    // ---- input staging (overlapped with cam computation; one sync covers both) ----
    if (full) {
        const float4* src4 = (const float4*)(rg + (size_t)idx0 * 19);
        for (int j = tid; j < TPB * 19 / 4; j += TPB) buf4[j] = src4[j];
    }

    if (tid == 0) {
        const float* E = ext + b * 16;
        const float* K = intr + b * 9;
#pragma unroll
        for (int i = 0; i < 3; i++) {
            cam.c2w[i * 3 + 0] = E[i * 4 + 0];
            cam.c2w[i * 3 + 1] = E[i * 4 + 1];
            cam.c2w[i * 3 + 2] = E[i * 4 + 2];
            cam.t[i]           = E[i * 4 + 3];
        }
        float k00 = K[0], k01 = K[1], k02 = K[2];
        float k10 = K[3], k11 = K[4], k12 = K[5];
        float k20 = K[6], k21 = K[7], k22 = K[8];
        float det = k00 * (k11 * k22 - k12 * k21)
                  - k01 * (k10 * k22 - k12 * k20)
                  + k02 * (k10 * k21 - k11 * k20);
        float id = 1.0f / det;
        cam.Kinv[0] = (k11 * k22 - k12 * k21) * id;
        cam.Kinv[1] = (k02 * k21 - k01 * k22) * id;
        cam.Kinv[2] = (k01 * k12 - k02 * k11) * id;
        cam.Kinv[3] = (k12 * k20 - k10 * k22) * id;
        cam.Kinv[4] = (k00 * k22 - k02 * k20) * id;
        cam.Kinv[5] = (k02 * k10 - k00 * k12) * id;
        cam.Kinv[6] = (k10 * k21 - k11 * k20) * id;
        cam.Kinv[7] = (k01 * k20 - k00 * k21) * id;
        cam.Kinv[8] = (k00 * k11 - k01 * k10) * id;

        unsigned hv = hptr[0], wv = wptr[0];
        float hf = (hv < 100000u) ? (float)hv : __uint_as_float(hv);
        float wf = (wv < 100000u) ? (float)wv : __uint_as_float(wv);
        float px = 1.0f / wf, py = 1.0f / hf;
        float det2 = k00 * k11 - k01 * k10;
        cam.mult = 0.1f * ((k11 * px - k01 * py) + (-k10 * px + k00 * py)) / det2;
    }
    __syncthreads();

    // Per-thread scalar inputs (coalesced already)
    float2 uv = make_float2(0.f, 0.f);
    float depth = 0.f, op = 0.f;
    if (live) {
        uv    = ((const float2*)coords)[idx];
        depth = depths[idx];
        op    = opac[idx];
    }

    // ---- first 7 rg values into registers (scales + quat); SH stays in smem ----
    float g0, g1, g2, qw, qx, qy, qz;
    const float* grow_s = buf + tid * 19;                 // smem row (full blocks)
    const float* grow_g = rg + (size_t)idx * 19;          // gmem row (tail blocks)
    if (full) {
        g0 = grow_s[0]; g1 = grow_s[1]; g2 = grow_s[2];
        qw = grow_s[3]; qx = grow_s[4]; qy = grow_s[5]; qz = grow_s[6];
    } else if (live) {
        g0 = grow_g[0]; g1 = grow_g[1]; g2 = grow_g[2];
        qw = grow_g[3]; qx = grow_g[4]; qy = grow_g[5]; qz = grow_g[6];
    } else {
        g0 = g1 = g2 = 0.f; qw = 1.f; qx = qy = qz = 0.f;
    }

    // ---- compute ----
    float dm = depth * cam.mult;
    float sc0 = (0.5f + 14.5f / (1.0f + __expf(-g0))) * dm;
    float sc1 = (0.5f + 14.5f / (1.0f + __expf(-g1))) * dm;
    float sc2 = (0.5f + 14.5f / (1.0f + __expf(-g2))) * dm;

    float qn = sqrtf(qw * qw + qx * qx + qy * qy + qz * qz) + 1e-8f;
    float qinv = 1.0f / qn;
    qw *= qinv; qx *= qinv; qy *= qinv; qz *= qinv;

    float R[9];
    R[0] = 1.f - 2.f * (qy * qy + qz * qz);
    R[1] = 2.f * (qx * qy - qw * qz);
    R[2] = 2.f * (qx * qz + qw * qy);
    R[3] = 2.f * (qx * qy + qw * qz);
    R[4] = 1.f - 2.f * (qx * qx + qz * qz);
    R[5] = 2.f * (qy * qz - qw * qx);
    R[6] = 2.f * (qx * qz - qw * qy);
    R[7] = 2.f * (qy * qz + qw * qx);
    R[8] = 1.f - 2.f * (qx * qx + qy * qy);

    float T[9];
#pragma unroll
    for (int i = 0; i < 3; i++) {
        T[i * 3 + 0] = (cam.c2w[i * 3 + 0] * R[0] + cam.c2w[i * 3 + 1] * R[3]
                      + cam.c2w[i * 3 + 2] * R[6]) * sc0;
        T[i * 3 + 1] = (cam.c2w[i * 3 + 0] * R[1] + cam.c2w[i * 3 + 1] * R[4]
                      + cam.c2w[i * 3 + 2] * R[7]) * sc1;
        T[i * 3 + 2] = (cam.c2w[i * 3 + 0] * R[2] + cam.c2w[i * 3 + 1] * R[5]
                      + cam.c2w[i * 3 + 2] * R[8]) * sc2;
    }
    float cov[9];
#pragma unroll
    for (int i = 0; i < 3; i++)
#pragma unroll
        for (int j = 0; j <= i; j++) {
            float v = T[i * 3 + 0] * T[j * 3 + 0]
                    + T[i * 3 + 1] * T[j * 3 + 1]
                    + T[i * 3 + 2] * T[j * 3 + 2];
            cov[i * 3 + j] = v;
            cov[j * 3 + i] = v;
        }

    float d0 = cam.Kinv[0] * uv.x + cam.Kinv[1] * uv.y + cam.Kinv[2];
    float d1 = cam.Kinv[3] * uv.x + cam.Kinv[4] * uv.y + cam.Kinv[5];
    float d2 = cam.Kinv[6] * uv.x + cam.Kinv[7] * uv.y + cam.Kinv[8];
    float rn = rsqrtf(d0 * d0 + d1 * d1 + d2 * d2);
    d0 *= rn; d1 *= rn; d2 *= rn;
    float m[3];
#pragma unroll
    for (int i = 0; i < 3; i++)
        m[i] = cam.t[i] + (cam.c2w[i * 3 + 0] * d0
                         + cam.c2w[i * 3 + 1] * d1
                         + cam.c2w[i * 3 + 2] * d2) * depth;

    // ---- harmonics: SH read from smem (full) / gmem (tail) just-in-time ----
    float har[12];
    const int pr[3] = {1, 2, 0};
#pragma unroll
    for (int c = 0; c < 3; c++) {
        float h0, s1, s2, s3;
        if (full) {
            h0 = grow_s[7 + c * 4 + 0];
            s1 = grow_s[7 + c * 4 + 1] * 0.025f;
            s2 = grow_s[7 + c * 4 + 2] * 0.025f;
            s3 = grow_s[7 + c * 4 + 3] * 0.025f;
        } else if (live) {
            h0 = grow_g[7 + c * 4 + 0];
            s1 = grow_g[7 + c * 4 + 1] * 0.025f;
            s2 = grow_g[7 + c * 4 + 2] * 0.025f;
            s3 = grow_g[7 + c * 4 + 3] * 0.025f;
        } else {
            h0 = s1 = s2 = s3 = 0.f;
        }
        har[c * 4 + 0] = h0;
#pragma unroll
        for (int i = 0; i < 3; i++) {
            int ri = pr[i];
            har[c * 4 + 1 + i] = cam.c2w[ri * 3 + 1] * s1
                               + cam.c2w[ri * 3 + 2] * s2
                               + cam.c2w[ri * 3 + 0] * s3;
        }
    }

    // ---- output section pointers ----
    float* means_o = out;                 // BN*3
    float* cov_o   = out + BN * 3;        // BN*9
    float* har_o   = out + BN * 12;       // BN*12
    float* op_o    = out + BN * 24;       // BN*1
    float* sc_o    = out + BN * 25;       // BN*3
    float* rot_o   = out + BN * 28;       // BN*4

    // direct stores (already coalesced): opacity (stride 1), rotations (float4/lane)
    if (live) {
        op_o[idx] = op;
        ((float4*)rot_o)[idx] = make_float4(qw, qx, qy, qz);
    }

    if (full) {
        __syncthreads();   // input region of buf fully consumed; safe to overwrite

        // ---- stage outputs: cov[0,9T) har[9T,21T) means[21T,24T) sc[24T,27T) ----
        // cov: scalar, stride 9 (odd) -> conflict-free
#pragma unroll
        for (int i = 0; i < 9; i++) buf[tid * 9 + i] = cov[i];
        // har: STS.128, float4-stride 3 -> conflict-free
        {
            float4* h4 = (float4*)(buf + 9 * TPB);
#pragma unroll
            for (int c = 0; c < 3; c++)
                h4[tid * 3 + c] = make_float4(har[c * 4 + 0], har[c * 4 + 1],
                                              har[c * 4 + 2], har[c * 4 + 3]);
        }
        // means & scales: scalar, stride 3 (odd) -> conflict-free
#pragma unroll
        for (int i = 0; i < 3; i++) {
            buf[21 * TPB + tid * 3 + i] = m[i];
        }
        buf[24 * TPB + tid * 3 + 0] = sc0;
        buf[24 * TPB + tid * 3 + 1] = sc1;
        buf[24 * TPB + tid * 3 + 2] = sc2;
        __syncthreads();

        // ---- single combined coalesced flush ----
        const float4* s4 = (const float4*)buf;
        float4* dc = (float4*)(cov_o   + (size_t)idx0 * 9);
        for (int j = tid; j < TPB * 9 / 4; j += TPB)  dc[j] = s4[j];
        float4* dh = (float4*)(har_o   + (size_t)idx0 * 12);
        for (int j = tid; j < TPB * 12 / 4; j += TPB) dh[j] = s4[TPB * 9 / 4 + j];
        float4* dmn = (float4*)(means_o + (size_t)idx0 * 3);
        if (tid < TPB * 3 / 4) dmn[tid] = s4[TPB * 21 / 4 + tid];
        float4* ds = (float4*)(sc_o    + (size_t)idx0 * 3);
        if (tid < TPB * 3 / 4) ds[tid] = s4[TPB * 24 / 4 + tid];
    } else if (live) {
#pragma unroll
        for (int i = 0; i < 3; i++) means_o[(size_t)idx * 3 + i] = m[i];
#pragma unroll
        for (int i = 0; i < 9; i++) cov_o[(size_t)idx * 9 + i] = cov[i];
#pragma unroll
        for (int i = 0; i < 12; i++) har_o[(size_t)idx * 12 + i] = har[i];
        sc_o[(size_t)idx * 3 + 0] = sc0;
        sc_o[(size_t)idx * 3 + 1] = sc1;
        sc_o[(size_t)idx * 3 + 2] = sc2;
    }
}

extern "C" void kernel_launch(void* const* d_in, const int* in_sizes, int n_in,
                              void* d_out, int out_size)
{
    const float* ext    = (const float*)d_in[0];
    const float* intr   = (const float*)d_in[1];
    const float* coords = (const float*)d_in[2];
    const float* depths = (const float*)d_in[3];
    const float* opac   = (const float*)d_in[4];
    const float* rg     = (const float*)d_in[5];
    const unsigned int* hptr = (const unsigned int*)d_in[6];
    const unsigned int* wptr = (const unsigned int*)d_in[7];
    float* out = (float*)d_out;

    const int B = in_sizes[0] / 16;            // extrinsics: B*1*4*4
    const int N = in_sizes[3] / B;             // depths: B*N

    dim3 grid((N + TPB - 1) / TPB, B);
    mono_gaussian_adapter_kernel<<<grid, TPB>>>(
        ext, intr, coords, depths, opac, rg, hptr, wptr, out, N);
}